// round 2
// baseline (speedup 1.0000x reference)
#include <cuda_runtime.h>
#include <cstdint>

// Problem constants (fixed shapes for SparseLinear_40278203302401)
#define BATCH 32
#define NNODES 100000
#define MNODES 100000
#define NNZ_TOTAL 3200000

// Scratch: x transposed to (N, B) and accumulator in (M, B) layout.
// Both are 12.8 MB -> L2 resident (126 MB L2).
__device__ float g_xt[NNODES * BATCH];
__device__ float g_yt[MNODES * BATCH];

// -------------------------------------------------------------------------
// Kernel 1: transpose x (B, N) -> x_t (N, B). N = 3125 * 32.
// blockIdx.x covers 32 columns of n. 32x8 threads.
// -------------------------------------------------------------------------
__global__ void k_transpose_x(const float* __restrict__ x, float* __restrict__ xt) {
    __shared__ float tile[32][33];
    const int n0 = blockIdx.x * 32;
    const int tx = threadIdx.x;          // 0..31
    const int ty = threadIdx.y;          // 0..7

    // read: tile[b][n_local] = x[b*N + n0 + tx], coalesced in tx
    #pragma unroll
    for (int i = ty; i < 32; i += 8) {
        tile[i][tx] = x[i * NNODES + n0 + tx];
    }
    __syncthreads();
    // write: xt[(n0+i)*32 + tx] = tile[tx][i]  (tx = batch), coalesced in tx
    #pragma unroll
    for (int i = ty; i < 32; i += 8) {
        xt[(n0 + i) * BATCH + tx] = tile[tx][i];
    }
}

// -------------------------------------------------------------------------
// Kernel 2: init y_t[m*32 + b] = bias[m]  (folds the bias add)
// -------------------------------------------------------------------------
__global__ void k_init_yt(const float* __restrict__ bias, float* __restrict__ yt) {
    const int idx = blockIdx.x * blockDim.x + threadIdx.x;
    if (idx < MNODES * BATCH) {
        yt[idx] = bias[idx >> 5];   // broadcast load per warp-row of 32
    }
}

// -------------------------------------------------------------------------
// Kernel 3: edge scatter. Each warp owns 32 consecutive edges.
// Lane i loads edge e0+i's (src, dst, val) coalesced, then the warp
// iterates over the 32 edges via shfl broadcast:
//   - gather:  one coalesced 128B read   x_t[src*32 + lane]
//   - scatter: one coalesced 128B RED    y_t[dst*32 + lane] += v * x
// -------------------------------------------------------------------------
__global__ void __launch_bounds__(256)
k_edges(const int* __restrict__ src, const int* __restrict__ dst,
        const float* __restrict__ val,
        const float* __restrict__ xt, float* __restrict__ yt) {
    const int warp_id = (blockIdx.x * blockDim.x + threadIdx.x) >> 5;
    const int lane = threadIdx.x & 31;
    const int e0 = warp_id * 32;
    if (e0 >= NNZ_TOTAL) return;

    const int my_e = e0 + lane;            // NNZ is a multiple of 32
    const int s = src[my_e];
    const int d = dst[my_e];
    const float v = val[my_e];

    #pragma unroll 8
    for (int j = 0; j < 32; j++) {
        const int   sj = __shfl_sync(0xffffffffu, s, j);
        const int   dj = __shfl_sync(0xffffffffu, d, j);
        const float vj = __shfl_sync(0xffffffffu, v, j);
        const float xv = __ldg(&xt[sj * BATCH + lane]);
        atomicAdd(&yt[dj * BATCH + lane], vj * xv);
    }
}

// -------------------------------------------------------------------------
// Kernel 4: transpose y_t (M, B) -> out (B, M). M = 3125 * 32.
// -------------------------------------------------------------------------
__global__ void k_write_out(const float* __restrict__ yt, float* __restrict__ out) {
    __shared__ float tile[32][33];
    const int m0 = blockIdx.x * 32;
    const int tx = threadIdx.x;
    const int ty = threadIdx.y;

    // read: yt[(m0+i)*32 + tx]  (tx = batch), coalesced in tx
    #pragma unroll
    for (int i = ty; i < 32; i += 8) {
        tile[i][tx] = yt[(m0 + i) * BATCH + tx];
    }
    __syncthreads();
    // write: out[b*M + m0 + tx] with b = i; value (m = m0+tx, b = i) = tile[tx][i]
    #pragma unroll
    for (int i = ty; i < 32; i += 8) {
        out[i * MNODES + m0 + tx] = tile[tx][i];
    }
}

// -------------------------------------------------------------------------
// Launch
// Inputs (metadata order): x (B*N f32), indices (2*NNZ i32), values (NNZ f32),
//                          bias (M f32). Output: (B, M) f32.
// -------------------------------------------------------------------------
extern "C" void kernel_launch(void* const* d_in, const int* in_sizes, int n_in,
                              void* d_out, int out_size) {
    const float* x      = (const float*)d_in[0];
    const int*   indices= (const int*)d_in[1];
    const float* values = (const float*)d_in[2];
    const float* bias   = (const float*)d_in[3];
    float* out = (float*)d_out;

    const int* src = indices;              // row 0
    const int* dst = indices + NNZ_TOTAL;  // row 1

    float* xt; cudaGetSymbolAddress((void**)&xt, g_xt);
    float* yt; cudaGetSymbolAddress((void**)&yt, g_yt);

    dim3 tblk(32, 8);

    // 1. transpose x
    k_transpose_x<<<NNODES / 32, tblk>>>(x, xt);

    // 2. init accumulator with bias
    k_init_yt<<<(MNODES * BATCH + 255) / 256, 256>>>(bias, yt);

    // 3. edge scatter: NNZ/32 warps, 8 warps per block
    const int n_warps = NNZ_TOTAL / 32;
    k_edges<<<(n_warps + 7) / 8, 256>>>(src, dst, values, xt, yt);

    // 4. write output
    k_write_out<<<MNODES / 32, tblk>>>(yt, out);
}

// round 4
// speedup vs baseline: 1.1055x; 1.1055x over previous
#include <cuda_runtime.h>
#include <cstdint>

// Problem constants (fixed shapes for SparseLinear_40278203302401)
#define BATCH 32
#define NNODES 100000
#define MNODES 100000
#define NNZ_TOTAL 3200000

// Scratch: x transposed to (N, B) and accumulator in (M, B) layout.
// Both are 12.8 MB -> L2 resident (126 MB L2).
__device__ float g_xt[NNODES * BATCH];
__device__ float g_yt[MNODES * BATCH];

__device__ __forceinline__ void red_add_v4(float* addr, float4 c) {
    asm volatile("red.global.add.v4.f32 [%0], {%1, %2, %3, %4};"
                 :: "l"(addr), "f"(c.x), "f"(c.y), "f"(c.z), "f"(c.w)
                 : "memory");
}

// -------------------------------------------------------------------------
// Kernel 1: transpose x (B=32, N) -> x_t (N, 32), float4 both directions.
// Block = 256 threads, tile = 32 n-cols x 32 batch.
//   read : thread t -> row b = t/8, c4 = t%8 : float4 x[b*N + n0 + c4*4]
//   write: thread t -> n_local = t/8, b4 = t%8 :
//          float4 {tile[b4*4+k][n_local]} -> xt[(n0+n_local)*32 + b4*4]
// -------------------------------------------------------------------------
__global__ void __launch_bounds__(256)
k_transpose_x(const float* __restrict__ x, float* __restrict__ xt) {
    __shared__ float tile[32][33];
    const int n0 = blockIdx.x * 32;
    const int t  = threadIdx.x;
    const int r  = t >> 3;        // 0..31
    const int c4 = t & 7;         // 0..7

    // coalesced float4 read of x: row r = batch, cols n0 + c4*4 .. +3
    float4 v = *(const float4*)&x[r * NNODES + n0 + c4 * 4];
    tile[r][c4 * 4 + 0] = v.x;
    tile[r][c4 * 4 + 1] = v.y;
    tile[r][c4 * 4 + 2] = v.z;
    tile[r][c4 * 4 + 3] = v.w;
    __syncthreads();

    // r = n_local, c4 = batch-quad
    float4 o;
    o.x = tile[c4 * 4 + 0][r];
    o.y = tile[c4 * 4 + 1][r];
    o.z = tile[c4 * 4 + 2][r];
    o.w = tile[c4 * 4 + 3][r];
    *(float4*)&xt[(n0 + r) * BATCH + c4 * 4] = o;
}

// -------------------------------------------------------------------------
// Kernel 2: init y_t[m*32 + b] = bias[m], float4 stores.
// M*32/4 = 800000 float4s; 8 float4s per m-row.
// -------------------------------------------------------------------------
__global__ void k_init_yt(const float* __restrict__ bias, float4* __restrict__ yt4) {
    const int idx = blockIdx.x * blockDim.x + threadIdx.x;
    if (idx < MNODES * 8) {
        const float b = __ldg(&bias[idx >> 3]);
        yt4[idx] = make_float4(b, b, b, b);
    }
}

// -------------------------------------------------------------------------
// Kernel 3: edge scatter, 8 lanes per edge, float4 gather + red.v4 scatter.
// Each warp owns 32 consecutive edges; 4 edges in flight per iteration
// (group g = lane>>3 handles edge e0 + j*4 + g; sub = lane&7 covers 4 batch).
// Per iteration (4 edges): 3 SHFL + 1 LDG.128 + 4 FMUL + 1 RED.v4.
// -------------------------------------------------------------------------
__global__ void __launch_bounds__(256)
k_edges(const int* __restrict__ src, const int* __restrict__ dst,
        const float* __restrict__ val,
        const float* __restrict__ xt, float* yt) {
    const int warp_id = (blockIdx.x * blockDim.x + threadIdx.x) >> 5;
    const int lane = threadIdx.x & 31;
    const int e0 = warp_id * 32;
    if (e0 >= NNZ_TOTAL) return;

    // lane i holds edge e0+i's metadata (coalesced loads; NNZ % 32 == 0)
    const int   s = src[e0 + lane];
    const int   d = dst[e0 + lane];
    const float v = val[e0 + lane];

    const int g   = lane >> 3;   // edge-group 0..3
    const int sub = lane & 7;    // batch-quad 0..7

    #pragma unroll
    for (int j = 0; j < 8; j++) {
        const int srcLane = j * 4 + g;
        const int   sj = __shfl_sync(0xffffffffu, s, srcLane);
        const int   dj = __shfl_sync(0xffffffffu, d, srcLane);
        const float vj = __shfl_sync(0xffffffffu, v, srcLane);

        const float4 xv = *(const float4*)&xt[sj * BATCH + sub * 4];
        float4 c;
        c.x = vj * xv.x;
        c.y = vj * xv.y;
        c.z = vj * xv.z;
        c.w = vj * xv.w;
        red_add_v4(&yt[dj * BATCH + sub * 4], c);
    }
}

// -------------------------------------------------------------------------
// Kernel 4: transpose y_t (M, 32) -> out (B=32, M), float4 both directions.
// -------------------------------------------------------------------------
__global__ void __launch_bounds__(256)
k_write_out(const float* __restrict__ yt, float* __restrict__ out) {
    __shared__ float tile[32][33];
    const int m0 = blockIdx.x * 32;
    const int t  = threadIdx.x;
    const int r  = t >> 3;        // 0..31
    const int c4 = t & 7;         // 0..7

    // coalesced float4 read of yt: row (m0+r), batches c4*4..+3
    float4 v = *(const float4*)&yt[(m0 + r) * BATCH + c4 * 4];
    tile[c4 * 4 + 0][r] = v.x;    // tile[b][m_local]
    tile[c4 * 4 + 1][r] = v.y;
    tile[c4 * 4 + 2][r] = v.z;
    tile[c4 * 4 + 3][r] = v.w;
    __syncthreads();

    // write out[b, m0 + m_local]: r = batch, c4 = m-quad
    float4 o;
    o.x = tile[r][c4 * 4 + 0];
    o.y = tile[r][c4 * 4 + 1];
    o.z = tile[r][c4 * 4 + 2];
    o.w = tile[r][c4 * 4 + 3];
    *(float4*)&out[r * MNODES + m0 + c4 * 4] = o;
}

// -------------------------------------------------------------------------
// Launch
// Inputs (metadata order): x (B*N f32), indices (2*NNZ i32), values (NNZ f32),
//                          bias (M f32). Output: (B, M) f32.
// -------------------------------------------------------------------------
extern "C" void kernel_launch(void* const* d_in, const int* in_sizes, int n_in,
                              void* d_out, int out_size) {
    const float* x      = (const float*)d_in[0];
    const int*   indices= (const int*)d_in[1];
    const float* values = (const float*)d_in[2];
    const float* bias   = (const float*)d_in[3];
    float* out = (float*)d_out;

    const int* src = indices;              // row 0
    const int* dst = indices + NNZ_TOTAL;  // row 1

    float* xt; cudaGetSymbolAddress((void**)&xt, g_xt);
    float* yt; cudaGetSymbolAddress((void**)&yt, g_yt);

    // 1. transpose x: N/32 tiles
    k_transpose_x<<<NNODES / 32, 256>>>(x, xt);

    // 2. init accumulator with bias (float4)
    k_init_yt<<<(MNODES * 8 + 255) / 256, 256>>>(bias, (float4*)yt);

    // 3. edge scatter: NNZ/32 warps, 8 warps per block
    const int n_warps = NNZ_TOTAL / 32;
    k_edges<<<(n_warps + 7) / 8, 256>>>(src, dst, values, xt, yt);

    // 4. write output
    k_write_out<<<MNODES / 32, 256>>>(yt, out);
}